// round 8
// baseline (speedup 1.0000x reference)
#include <cuda_runtime.h>
#include <math.h>
#include <stdint.h>

#define HD      1024
#define NROWS   50000
#define NCTA    144                 // 1 CTA/SM, co-resident on >=144 SMs
#define NTHR    288                 // 8 consumer warps + 1 producer warp
#define NP4     (HD / 4)            // 256 float4 per row
#define TROWS   8                   // rows per pipeline stage
#define STAGES  6
#define TILE_BYTES (TROWS * HD * 4) // 32 KB
#define NTILES  (NROWS / TROWS)     // 6250 (exact)
#define DYN_SMEM (STAGES * TILE_BYTES)

// Scratch (__device__ globals)
__device__ float  g_q[HD];
__device__ float  g_d2[HD];                  // W2@h_t + b2
__device__ float4 g_epartT[NP4 * NCTA];      // [position][cta]
__device__ float  g_Zpart[NCTA];
__device__ float  g_es[HD];
__device__ float  g_Zsum;
__device__ unsigned g_ctr[4];                // monotonic barrier counters

// Grid barrier, graph-replay safe (counter never resets).
__device__ __forceinline__ void gbar(int k) {
    __syncthreads();
    if (threadIdx.x == 0) {
        __threadfence();
        unsigned old = atomicAdd(&g_ctr[k], 1u);
        unsigned tgt = old - (old % NCTA) + NCTA;
        while (*(volatile unsigned*)&g_ctr[k] < tgt) __nanosleep(32);
    }
    __syncthreads();
    __threadfence();
}

__device__ __forceinline__ void mbar_init(unsigned a, unsigned cnt) {
    asm volatile("mbarrier.init.shared.b64 [%0], %1;" :: "r"(a), "r"(cnt) : "memory");
}
__device__ __forceinline__ void mbar_arrive(unsigned a) {
    asm volatile("mbarrier.arrive.shared.b64 _, [%0];" :: "r"(a) : "memory");
}
__device__ __forceinline__ void mbar_expect_tx(unsigned a, unsigned bytes) {
    asm volatile("mbarrier.arrive.expect_tx.shared.b64 _, [%0], %1;"
                 :: "r"(a), "r"(bytes) : "memory");
}
__device__ __forceinline__ void mwait(unsigned a, unsigned parity) {
    asm volatile(
        "{\n\t.reg .pred P;\n\t"
        "W_%=:\n\t"
        "mbarrier.try_wait.parity.acquire.cta.shared::cta.b64 P, [%0], %1, 0x989680;\n\t"
        "@P bra D_%=;\n\t"
        "bra W_%=;\n\t"
        "D_%=:\n\t}"
        :: "r"(a), "r"(parity) : "memory");
}
__device__ __forceinline__ void bulk_g2s(unsigned dst, const void* src,
                                         unsigned bytes, unsigned mbar) {
    asm volatile("cp.async.bulk.shared::cluster.global.mbarrier::complete_tx::bytes "
                 "[%0], [%1], %2, [%3];"
                 :: "r"(dst), "l"(src), "r"(bytes), "r"(mbar) : "memory");
}

__global__ __launch_bounds__(NTHR, 1) void fused(
    const float* __restrict__ H,  const float* __restrict__ ht,
    const float* __restrict__ W0, const float* __restrict__ b0,
    const float* __restrict__ W1, const float* __restrict__ b1,
    const float* __restrict__ W2, const float* __restrict__ b2,
    float* __restrict__ out)
{
    extern __shared__ float4 dyn[];            // STAGES x TROWS x NP4 tiles

    __shared__ float4 sv[NP4];                 // ht / e_s
    __shared__ float4 sred[2][160];            // phase-3 reduce (2 positions/CTA)
    __shared__ float  sZr[256];
    __shared__ float  sZ[8];
    __shared__ float  sZtot;
    __shared__ uint64_t mb_full[STAGES], mb_empty[STAGES];

    const int tid  = threadIdx.x;
    const int wid  = tid >> 5, lane = tid & 31;
    const int cta  = blockIdx.x;

    unsigned full_a[STAGES], empty_a[STAGES];
#pragma unroll
    for (int s = 0; s < STAGES; s++) {
        full_a[s]  = (unsigned)__cvta_generic_to_shared(&mb_full[s]);
        empty_a[s] = (unsigned)__cvta_generic_to_shared(&mb_empty[s]);
    }
    if (tid == 0) {
#pragma unroll
        for (int s = 0; s < STAGES; s++) {
            mbar_init(full_a[s], 1);           // completed by TMA tx
            mbar_init(empty_a[s], 8);          // 8 consumer warps
        }
    }

    // ---------------- Phase 1: q = W0@ht + b0 ; d2 = W2@ht + b2 -------------
    if (tid < NP4) sv[tid] = ((const float4*)ht)[tid];
    __syncthreads();                           // also publishes mbarrier init
    for (int gw = cta * 9 + wid; gw < 2048; gw += NCTA * 9) {
        int j = gw & 1023;
        const float* W = (gw < 1024) ? W0 : W2;
        const float* b = (gw < 1024) ? b0 : b2;
        const float4* wr = (const float4*)(W + (size_t)j * HD);
        float4 w[8];
#pragma unroll
        for (int k = 0; k < 8; k++) w[k] = wr[lane + 32 * k];   // MLP=8
        float s = 0.f;
#pragma unroll
        for (int k = 0; k < 8; k++) {
            float4 h4 = sv[lane + 32 * k];
            s = fmaf(w[k].x, h4.x, s); s = fmaf(w[k].y, h4.y, s);
            s = fmaf(w[k].z, h4.z, s); s = fmaf(w[k].w, h4.w, s);
        }
#pragma unroll
        for (int o = 16; o; o >>= 1) s += __shfl_xor_sync(0xffffffffu, s, o);
        if (lane == 0) { if (gw < 1024) g_q[j] = s + b[j]; else g_d2[j] = s + b[j]; }
    }
    gbar(0);

    // ---------------- Phase 2: TMA-pipelined pass over H --------------------
    unsigned dyn_base = (unsigned)__cvta_generic_to_shared(dyn);

    if (wid == 8) {
        // Producer: lane 0 streams tiles through the 6-stage ring.
        if (lane == 0) {
            int s = 0; unsigned pp = 1;        // phase=1: first empty-wait passes
            for (int t = cta; t < NTILES; t += NCTA) {
                mwait(empty_a[s], pp);
                mbar_expect_tx(full_a[s], TILE_BYTES);
                bulk_g2s(dyn_base + s * TILE_BYTES,
                         H + (size_t)t * TROWS * HD, TILE_BYTES, full_a[s]);
                if (++s == STAGES) { s = 0; pp ^= 1; }
            }
        }
        // producer warp idles until phase-2 end barrier
    } else {
        // Consumers: warp w owns row w of each tile.
        float4 q4[8];
#pragma unroll
        for (int k = 0; k < 8; k++)
            q4[k] = __ldcg(((const float4*)g_q) + lane + 32 * k);

        float4 e[8];
#pragma unroll
        for (int k = 0; k < 8; k++) e[k] = make_float4(0.f, 0.f, 0.f, 0.f);
        float Z = 0.f;

        int s = 0; unsigned cp = 0;
        for (int t = cta; t < NTILES; t += NCTA) {
            mwait(full_a[s], cp);
            const float4* rowp = dyn + (s * TROWS + wid) * NP4;
            float4 r[8];
#pragma unroll
            for (int k = 0; k < 8; k++) r[k] = rowp[lane + 32 * k];
            __syncwarp();
            if (lane == 0) mbar_arrive(empty_a[s]);   // free stage ASAP

            float sdot = 0.f;
#pragma unroll
            for (int k = 0; k < 8; k++) {
                sdot = fmaf(r[k].x, q4[k].x, sdot); sdot = fmaf(r[k].y, q4[k].y, sdot);
                sdot = fmaf(r[k].z, q4[k].z, sdot); sdot = fmaf(r[k].w, q4[k].w, sdot);
            }
#pragma unroll
            for (int o = 16; o; o >>= 1) sdot += __shfl_xor_sync(0xffffffffu, sdot, o);

            // double exp; softmax(t)=exp(t)/sum(exp(t)) exactly, t bounded.
            float u = expf(expf(sdot));
            Z += u;
#pragma unroll
            for (int k = 0; k < 8; k++) {
                e[k].x = fmaf(u, r[k].x, e[k].x);
                e[k].y = fmaf(u, r[k].y, e[k].y);
                e[k].z = fmaf(u, r[k].z, e[k].z);
                e[k].w = fmaf(u, r[k].w, e[k].w);
            }
            if (++s == STAGES) { s = 0; cp ^= 1; }
        }

        // stash per-warp partials
        if (lane == 0) sZ[wid] = Z;
#pragma unroll
        for (int k = 0; k < 8; k++) {
            // temporarily hold in registers; written to smem after syncthreads
        }
        __syncthreads();                       // ring dead; overlay partials
        float4* wbuf = dyn;                    // [8][256]
#pragma unroll
        for (int k = 0; k < 8; k++) wbuf[wid * NP4 + lane + 32 * k] = e[k];
    }
    if (wid == 8) __syncthreads();             // producer matches consumer sync
    __syncthreads();

    {   // CTA reduce of 8 warp partials -> g_epartT / g_Zpart
        float4* wbuf = dyn;
        if (tid < NP4) {
            float4 acc = wbuf[tid];
#pragma unroll
            for (int w = 1; w < 8; w++) {
                float4 v = wbuf[w * NP4 + tid];
                acc.x += v.x; acc.y += v.y; acc.z += v.z; acc.w += v.w;
            }
            g_epartT[tid * NCTA + cta] = acc;  // position-major
        }
        if (tid == 0) {
            float z = 0.f;
#pragma unroll
            for (int w = 0; w < 8; w++) z += sZ[w];
            g_Zpart[cta] = z;
        }
    }
    gbar(1);

    // ---------------- Phase 3: reduce NCTA partials -> g_es, g_Zsum ---------
    if (cta < 128) {                           // 2 positions per CTA
        int g = tid / 144, t = tid - g * 144;  // g in {0,1}, t in [0,144)
        int p = 2 * cta + g;
        sred[g][t] = __ldcg(&g_epartT[(size_t)p * NCTA + t]);
        __syncthreads();
        if (tid < 32) {                        // fold 144 -> 128
            int g2 = tid / 16, t2 = tid % 16;
            float4 b = sred[g2][128 + t2], x = sred[g2][t2];
            x.x += b.x; x.y += b.y; x.z += b.z; x.w += b.w;
            sred[g2][t2] = x;
        }
        __syncthreads();
#pragma unroll
        for (int o = 64; o; o >>= 1) {
            if (tid < 2 * o) {
                int g2 = tid / o, t2 = tid % o;
                float4 b = sred[g2][t2 + o], x = sred[g2][t2];
                x.x += b.x; x.y += b.y; x.z += b.z; x.w += b.w;
                sred[g2][t2] = x;
            }
            __syncthreads();
        }
        if (tid < 2) ((float4*)g_es)[2 * cta + tid] = sred[tid][0];
    } else if (cta == 128) {                   // partition function
        if (tid < 256) sZr[tid] = (tid < NCTA) ? __ldcg(&g_Zpart[tid]) : 0.f;
        __syncthreads();
#pragma unroll
        for (int o = 128; o; o >>= 1) {
            if (tid < o) sZr[tid] += sZr[tid + o];
            __syncthreads();
        }
        if (tid == 0) g_Zsum = sZr[0];
    }
    gbar(2);

    // ---------------- Phase 4: out = tanh(W1@e_s/Z + b1 + d2) ---------------
    if (cta < 128) {
        if (tid < NP4) sv[tid] = __ldcg(((const float4*)g_es) + tid);
        if (tid == 0) sZtot = __ldcg(&g_Zsum);
        __syncthreads();
        if (wid < 8) {
            int j = cta * 8 + wid;             // 0..1023
            const float4* w1r = (const float4*)(W1 + (size_t)j * HD);
            float4 a[8];
#pragma unroll
            for (int k = 0; k < 8; k++) a[k] = w1r[lane + 32 * k];  // MLP=8
            float d1 = 0.f;
#pragma unroll
            for (int k = 0; k < 8; k++) {
                float4 v = sv[lane + 32 * k];
                d1 = fmaf(a[k].x, v.x, d1); d1 = fmaf(a[k].y, v.y, d1);
                d1 = fmaf(a[k].z, v.z, d1); d1 = fmaf(a[k].w, v.w, d1);
            }
#pragma unroll
            for (int o = 16; o; o >>= 1) d1 += __shfl_xor_sync(0xffffffffu, d1, o);
            if (lane == 0)
                out[j] = tanhf(d1 / sZtot + b1[j] + __ldcg(g_d2 + j));
        }
    }
}

// ---------------------------------------------------------------------------
extern "C" void kernel_launch(void* const* d_in, const int* in_sizes, int n_in,
                              void* d_out, int out_size) {
    const float* H  = (const float*)d_in[0];
    const float* ht = (const float*)d_in[1];
    const float* W0 = (const float*)d_in[2];
    const float* b0 = (const float*)d_in[3];
    const float* W1 = (const float*)d_in[4];
    const float* b1 = (const float*)d_in[5];
    const float* W2 = (const float*)d_in[6];
    const float* b2 = (const float*)d_in[7];
    float* out = (float*)d_out;

    static int configured = 0;
    if (!configured) {
        cudaFuncSetAttribute(fused, cudaFuncAttributeMaxDynamicSharedMemorySize,
                             DYN_SMEM);
        configured = 1;
    }
    fused<<<NCTA, NTHR, DYN_SMEM>>>(H, ht, W0, b0, W1, b1, W2, b2, out);
}

// round 10
// speedup vs baseline: 1.1126x; 1.1126x over previous
#include <cuda_runtime.h>
#include <math.h>

#define HD      1024
#define NROWS   50000
#define GRID    288                  // 2 CTAs/SM on >=144 SMs: co-residency safe
#define WARPS_B 8
#define NP4     (HD / 4)             // 256 float4 per vector
#define CHUNK_ROWS 16                // per-CTA steal quantum (2 rows/warp)
#define NCHUNK  (NROWS / CHUNK_ROWS) // 3125 exact

// Scratch (__device__ globals)
__device__ float  g_qh[2][HD];                  // half-row partial dots of W0@ht
__device__ float  g_d2[HD];                     // W2@h_t + b2
__device__ float4 g_epartT[NP4 * GRID];         // [position][cta]
__device__ float  g_Zpart[GRID];
__device__ float  g_es[HD];
__device__ float  g_Zsum;
__device__ unsigned g_ctr[4];                   // barrier counters (monotonic)
__device__ unsigned g_tile;                     // steal counter (reset each launch)

// Grid-wide barrier, graph-replay safe: counter never resets.
__device__ __forceinline__ void gbar(int k) {
    __syncthreads();
    if (threadIdx.x == 0) {
        __threadfence();
        unsigned old = atomicAdd(&g_ctr[k], 1u);
        unsigned target = old - (old % GRID) + GRID;
        while (*(volatile unsigned*)&g_ctr[k] < target) { }
    }
    __syncthreads();
    __threadfence();
}

__device__ __forceinline__ float4 ldcs4(const float4* p) {
    float4 v;
    asm volatile("ld.global.cs.v4.f32 {%0,%1,%2,%3}, [%4];"
                 : "=f"(v.x), "=f"(v.y), "=f"(v.z), "=f"(v.w) : "l"(p));
    return v;
}

__global__ __launch_bounds__(256, 2) void fused(
    const float* __restrict__ H,  const float* __restrict__ ht,
    const float* __restrict__ W0, const float* __restrict__ b0,
    const float* __restrict__ W1, const float* __restrict__ b1,
    const float* __restrict__ W2, const float* __restrict__ b2,
    float* __restrict__ out)
{
    __shared__ float4 sv[NP4];                 // ht -> q -> e_s (phase-local)
    __shared__ float4 se[WARPS_B][NP4];        // warp partials / reduce buf
    __shared__ float  sZ[WARPS_B];
    __shared__ float  sZtot;
    __shared__ int    s_chunk;

    const int tid  = threadIdx.x;
    const int wid  = tid >> 5, lane = tid & 31;
    const int cta  = blockIdx.x;

    // ---------------- Phase 1: q halves only (2 warps per W0 row) ------------
    sv[tid] = ((const float4*)ht)[tid];
    if (cta == 0 && tid == 0) g_tile = 0;      // steal-counter reset (pre-gbar)
    __syncthreads();
    {
        int gw = cta * WARPS_B + wid;          // 0..2303 ; 2048 half-rows
        if (gw < 2048) {
            int j = gw >> 1, half = gw & 1;
            const float4* wr = (const float4*)(W0 + (size_t)j * HD) + half * 128;
            float4 w[4];
#pragma unroll
            for (int k = 0; k < 4; k++) w[k] = wr[lane + 32 * k];   // MLP=4
            const float4* hh = sv + half * 128;
            float s = 0.f;
#pragma unroll
            for (int k = 0; k < 4; k++) {
                float4 h4 = hh[lane + 32 * k];
                s = fmaf(w[k].x, h4.x, s); s = fmaf(w[k].y, h4.y, s);
                s = fmaf(w[k].z, h4.z, s); s = fmaf(w[k].w, h4.w, s);
            }
#pragma unroll
            for (int o = 16; o; o >>= 1) s += __shfl_xor_sync(0xffffffffu, s, o);
            if (lane == 0) g_qh[half][j] = s;
        }
    }
    gbar(0);

    // ---------------- Phase 2: d2 prologue + work-stealing pass over H -------
    {   // build q in smem: q[j] = qh0[j] + qh1[j] + b0[j]
        float4 a = __ldcg(((const float4*)g_qh[0]) + tid);
        float4 b = __ldcg(((const float4*)g_qh[1]) + tid);
        float4 c = __ldcg(((const float4*)b0) + tid);
        sv[tid] = make_float4(a.x + b.x + c.x, a.y + b.y + c.y,
                              a.z + b.z + c.z, a.w + b.w + c.w);
    }
    __syncthreads();

    // d2 = W2@ht + b2 on CTAs 0..127 (start delay absorbed by stealing)
    if (cta < 128) {
        int j = cta * WARPS_B + wid;           // 0..1023
        const float4* wr = (const float4*)(W2 + (size_t)j * HD);
        float4 w[8];
#pragma unroll
        for (int k = 0; k < 8; k++) w[k] = wr[lane + 32 * k];       // MLP=8
        float s = 0.f;
#pragma unroll
        for (int k = 0; k < 8; k++) {
            float4 h4 = __ldcg(((const float4*)ht) + lane + 32 * k); // L2-hot
            s = fmaf(w[k].x, h4.x, s); s = fmaf(w[k].y, h4.y, s);
            s = fmaf(w[k].z, h4.z, s); s = fmaf(w[k].w, h4.w, s);
        }
#pragma unroll
        for (int o = 16; o; o >>= 1) s += __shfl_xor_sync(0xffffffffu, s, o);
        if (lane == 0) g_d2[j] = s + b2[j];
    }

    float4 e[8];
#pragma unroll
    for (int k = 0; k < 8; k++) e[k] = make_float4(0.f, 0.f, 0.f, 0.f);
    float Z = 0.f;

    for (;;) {
        __syncthreads();                       // prior s_chunk read complete
        if (tid == 0) s_chunk = (int)atomicAdd(&g_tile, 1u);
        __syncthreads();
        int c = s_chunk;
        if (c >= NCHUNK) break;

        int row = c * CHUNK_ROWS + 2 * wid;    // 2 rows per warp
        const float4* h0 = (const float4*)(H + (size_t)row * HD);
        const float4* h1 = (const float4*)(H + (size_t)(row + 1) * HD);

        float4 r0[8], r1[8];
#pragma unroll
        for (int k = 0; k < 8; k++) r0[k] = ldcs4(h0 + lane + 32 * k);
#pragma unroll
        for (int k = 0; k < 8; k++) r1[k] = ldcs4(h1 + lane + 32 * k);

        float s0 = 0.f, s1 = 0.f;
#pragma unroll
        for (int k = 0; k < 8; k++) {
            float4 q4 = sv[lane + 32 * k];
            s0 = fmaf(r0[k].x, q4.x, s0); s0 = fmaf(r0[k].y, q4.y, s0);
            s0 = fmaf(r0[k].z, q4.z, s0); s0 = fmaf(r0[k].w, q4.w, s0);
            s1 = fmaf(r1[k].x, q4.x, s1); s1 = fmaf(r1[k].y, q4.y, s1);
            s1 = fmaf(r1[k].z, q4.z, s1); s1 = fmaf(r1[k].w, q4.w, s1);
        }
#pragma unroll
        for (int o = 16; o; o >>= 1) {
            s0 += __shfl_xor_sync(0xffffffffu, s0, o);
            s1 += __shfl_xor_sync(0xffffffffu, s1, o);
        }

        // double exp; softmax(t)=exp(t)/sum(exp(t)) exactly, t bounded.
        float u0 = expf(expf(s0));
        float u1 = expf(expf(s1));
        Z += u0 + u1;
#pragma unroll
        for (int k = 0; k < 8; k++) {
            e[k].x = fmaf(u0, r0[k].x, fmaf(u1, r1[k].x, e[k].x));
            e[k].y = fmaf(u0, r0[k].y, fmaf(u1, r1[k].y, e[k].y));
            e[k].z = fmaf(u0, r0[k].z, fmaf(u1, r1[k].z, e[k].z));
            e[k].w = fmaf(u0, r0[k].w, fmaf(u1, r1[k].w, e[k].w));
        }
    }

    // CTA-level deterministic reduce of the 8 warp partials
#pragma unroll
    for (int k = 0; k < 8; k++) se[wid][lane + 32 * k] = e[k];
    if (lane == 0) sZ[wid] = Z;
    __syncthreads();
    {
        float4 acc = se[0][tid];
#pragma unroll
        for (int w = 1; w < WARPS_B; w++) {
            float4 v = se[w][tid];
            acc.x += v.x; acc.y += v.y; acc.z += v.z; acc.w += v.w;
        }
        g_epartT[tid * GRID + cta] = acc;      // position-major for phase 3
        if (tid == 0) {
            float z = 0.f;
#pragma unroll
            for (int w = 0; w < WARPS_B; w++) z += sZ[w];
            g_Zpart[cta] = z;
        }
    }
    gbar(1);

    // ---------------- Phase 3 (CTAs 0..127, CTA 256) + Phase-4 preload ------
    float4 a[8]; float bj = 0.f, dj = 0.f;     // phase-4 preloads (CTAs 128..255)
    if (cta >= 128 && cta < 256) {
        int j = (cta - 128) * WARPS_B + wid;   // 0..1023
        const float4* w1r = (const float4*)(W1 + (size_t)j * HD);
#pragma unroll
        for (int k = 0; k < 8; k++) a[k] = w1r[lane + 32 * k];  // 4MB overlaps ph3
        if (lane == 0) { bj = b1[j]; dj = __ldcg(g_d2 + j); }
    } else if (cta < 128) {                    // reduce 2 positions per CTA
        int g = tid >> 7, t0 = tid & 127;      // g in {0,1}
        int p = 2 * cta + g;
        const float4* src = g_epartT + (size_t)p * GRID;
        float4 acc = __ldcg(src + t0);
        {   float4 v = __ldcg(src + t0 + 128);
            acc.x += v.x; acc.y += v.y; acc.z += v.z; acc.w += v.w; }
        if (t0 < GRID - 256) {
            float4 v = __ldcg(src + t0 + 256);
            acc.x += v.x; acc.y += v.y; acc.z += v.z; acc.w += v.w;
        }
        float4* red = &se[g * 2][0];           // two disjoint 128-entry buffers
        red[t0] = acc;
        __syncthreads();
#pragma unroll
        for (int o = 64; o; o >>= 1) {
            if (t0 < o) {
                float4 v = red[t0 + o], t = red[t0];
                t.x += v.x; t.y += v.y; t.z += v.z; t.w += v.w;
                red[t0] = t;
            }
            __syncthreads();
        }
        if (t0 == 0) ((float4*)g_es)[p] = red[0];
    } else if (cta == 256) {                   // partition function
        if (wid == 0) {
            float z = 0.f;
            for (int b = lane; b < GRID; b += 32) z += __ldcg(g_Zpart + b);
#pragma unroll
            for (int o = 16; o; o >>= 1) z += __shfl_xor_sync(0xffffffffu, z, o);
            if (lane == 0) g_Zsum = z;
        }
    }
    gbar(2);

    // ---------------- Phase 4: out = tanh(W1@e_s/Z + b1 + d2) ----------------
    if (cta >= 128 && cta < 256) {
        int j = (cta - 128) * WARPS_B + wid;
        sv[tid] = __ldcg(((const float4*)g_es) + tid);
        if (tid == 0) sZtot = __ldcg(&g_Zsum);
        __syncthreads();

        float d1 = 0.f;
#pragma unroll
        for (int k = 0; k < 8; k++) {
            float4 v = sv[lane + 32 * k];
            d1 = fmaf(a[k].x, v.x, d1); d1 = fmaf(a[k].y, v.y, d1);
            d1 = fmaf(a[k].z, v.z, d1); d1 = fmaf(a[k].w, v.w, d1);
        }
#pragma unroll
        for (int o = 16; o; o >>= 1) d1 += __shfl_xor_sync(0xffffffffu, d1, o);
        if (lane == 0)
            out[j] = tanhf(d1 / sZtot + bj + dj);
    }
}

// ---------------------------------------------------------------------------
extern "C" void kernel_launch(void* const* d_in, const int* in_sizes, int n_in,
                              void* d_out, int out_size) {
    const float* H  = (const float*)d_in[0];
    const float* ht = (const float*)d_in[1];
    const float* W0 = (const float*)d_in[2];
    const float* b0 = (const float*)d_in[3];
    const float* W1 = (const float*)d_in[4];
    const float* b1 = (const float*)d_in[5];
    const float* W2 = (const float*)d_in[6];
    const float* b2 = (const float*)d_in[7];
    float* out = (float*)d_out;

    fused<<<GRID, 256>>>(H, ht, W0, b0, W1, b1, W2, b2, out);
}

// round 11
// speedup vs baseline: 1.2508x; 1.1242x over previous
#include <cuda_runtime.h>
#include <math.h>

#define HD      1024
#define NROWS   50000
#define GRID    288                  // 2 CTAs/SM on >=144 SMs: co-residency safe
#define WARPS_B 8
#define TOT_WARPS (GRID * WARPS_B)   // 2304
#define NP4     (HD / 4)             // 256 float4 per vector

// Scratch (__device__ globals)
__device__ float  g_q[HD];
__device__ float  g_d2[HD];                     // W2@h_t + b2
__device__ float4 g_epartT[NP4 * GRID];         // [position][cta]
__device__ float  g_Zpart[GRID];
__device__ float  g_es[HD];
__device__ float  g_Zsum;
__device__ unsigned g_ctr[4];                   // barrier counters (monotonic)

// Grid-wide barrier, graph-replay safe: counter never resets.
__device__ __forceinline__ void gbar(int k) {
    __syncthreads();
    if (threadIdx.x == 0) {
        __threadfence();
        unsigned old = atomicAdd(&g_ctr[k], 1u);
        unsigned target = old - (old % GRID) + GRID;
        while (*(volatile unsigned*)&g_ctr[k] < target) { }
    }
    __syncthreads();
    __threadfence();
}

__device__ __forceinline__ float4 ldcs4(const float4* p) {
    float4 v;
    asm volatile("ld.global.cs.v4.f32 {%0,%1,%2,%3}, [%4];"
                 : "=f"(v.x), "=f"(v.y), "=f"(v.z), "=f"(v.w) : "l"(p));
    return v;
}
__device__ __forceinline__ void pfL2(const void* p) {
    asm volatile("prefetch.global.L2 [%0];" :: "l"(p));
}

__global__ __launch_bounds__(256, 2) void fused(
    const float* __restrict__ H,  const float* __restrict__ ht,
    const float* __restrict__ W0, const float* __restrict__ b0,
    const float* __restrict__ W1, const float* __restrict__ b1,
    const float* __restrict__ W2, const float* __restrict__ b2,
    float* __restrict__ out)
{
    __shared__ float4 sv[NP4];                 // ht -> q -> e_s (phase-local)
    __shared__ float4 se[WARPS_B][NP4];        // warp partials / reduce buf
    __shared__ float  sZ[WARPS_B];
    __shared__ float  sZtot;

    const int tid  = threadIdx.x;
    const int wid  = tid >> 5, lane = tid & 31;
    const int cta  = blockIdx.x;
    const int gw   = cta * WARPS_B + wid;      // global warp id, 0..2303

    // ---------------- Phase 1: q = W0@ht + b0 ; d2 = W2@ht + b2 --------------
    sv[tid] = ((const float4*)ht)[tid];
    __syncthreads();
    {
        if (gw < 2048) {
            int j = gw & 1023;
            const float* W = (gw < 1024) ? W0 : W2;
            const float* b = (gw < 1024) ? b0 : b2;
            const float4* wr = (const float4*)(W + (size_t)j * HD);
            float4 w[8];
#pragma unroll
            for (int k = 0; k < 8; k++) w[k] = wr[lane + 32 * k];  // MLP=8

            // Prefetch this warp's first 3 phase-2 iterations into L2 while
            // phase 1 is latency-bound (spare DRAM BW). 128B per lane per row.
#pragma unroll
            for (int it = 0; it < 3; it++) {
                long r0 = 2L * gw + it * (2L * TOT_WARPS);
                if (r0 + 1 < NROWS) {
                    pfL2(H + r0 * HD + lane * 32);
                    pfL2(H + (r0 + 1) * HD + lane * 32);
                }
            }

            float s = 0.f;
#pragma unroll
            for (int k = 0; k < 8; k++) {
                float4 h4 = sv[lane + 32 * k];
                s = fmaf(w[k].x, h4.x, s); s = fmaf(w[k].y, h4.y, s);
                s = fmaf(w[k].z, h4.z, s); s = fmaf(w[k].w, h4.w, s);
            }
#pragma unroll
            for (int o = 16; o; o >>= 1) s += __shfl_xor_sync(0xffffffffu, s, o);
            if (lane == 0) { if (gw < 1024) g_q[j] = s + b[j]; else g_d2[j] = s + b[j]; }
        } else {
            // idle warps: prefetch too
#pragma unroll
            for (int it = 0; it < 3; it++) {
                long r0 = 2L * gw + it * (2L * TOT_WARPS);
                if (r0 + 1 < NROWS) {
                    pfL2(H + r0 * HD + lane * 32);
                    pfL2(H + (r0 + 1) * HD + lane * 32);
                }
            }
        }
    }
    gbar(0);

    // ---------------- Phase 2: pass over H, TWO rows per warp-iteration ------
    sv[tid] = __ldcg(((const float4*)g_q) + tid);
    __syncthreads();

    float4 e[8];
#pragma unroll
    for (int k = 0; k < 8; k++) e[k] = make_float4(0.f, 0.f, 0.f, 0.f);
    float Z = 0.f;

    for (int row = 2 * gw; row < NROWS; row += 2 * TOT_WARPS) {
        const float4* h0 = (const float4*)(H + (size_t)row * HD);
        const float4* h1 = (const float4*)(H + (size_t)(row + 1) * HD);

        float4 r0[8], r1[8];
#pragma unroll
        for (int k = 0; k < 8; k++) r0[k] = ldcs4(h0 + lane + 32 * k);  // 16 loads
#pragma unroll
        for (int k = 0; k < 8; k++) r1[k] = ldcs4(h1 + lane + 32 * k);  // front-batched

        float s0 = 0.f, s1 = 0.f;
#pragma unroll
        for (int k = 0; k < 8; k++) {
            float4 q4 = sv[lane + 32 * k];
            s0 = fmaf(r0[k].x, q4.x, s0); s0 = fmaf(r0[k].y, q4.y, s0);
            s0 = fmaf(r0[k].z, q4.z, s0); s0 = fmaf(r0[k].w, q4.w, s0);
            s1 = fmaf(r1[k].x, q4.x, s1); s1 = fmaf(r1[k].y, q4.y, s1);
            s1 = fmaf(r1[k].z, q4.z, s1); s1 = fmaf(r1[k].w, q4.w, s1);
        }
#pragma unroll
        for (int o = 16; o; o >>= 1) {
            s0 += __shfl_xor_sync(0xffffffffu, s0, o);
            s1 += __shfl_xor_sync(0xffffffffu, s1, o);
        }

        // double exp; softmax(t)=exp(t)/sum(exp(t)) exactly, t bounded.
        float u0 = expf(expf(s0));
        float u1 = expf(expf(s1));
        Z += u0 + u1;
#pragma unroll
        for (int k = 0; k < 8; k++) {
            e[k].x = fmaf(u0, r0[k].x, fmaf(u1, r1[k].x, e[k].x));
            e[k].y = fmaf(u0, r0[k].y, fmaf(u1, r1[k].y, e[k].y));
            e[k].z = fmaf(u0, r0[k].z, fmaf(u1, r1[k].z, e[k].z));
            e[k].w = fmaf(u0, r0[k].w, fmaf(u1, r1[k].w, e[k].w));
        }
    }

    // CTA-level deterministic reduce of the 8 warp partials
#pragma unroll
    for (int k = 0; k < 8; k++) se[wid][lane + 32 * k] = e[k];
    if (lane == 0) sZ[wid] = Z;
    __syncthreads();
    {
        float4 acc = se[0][tid];
#pragma unroll
        for (int w = 1; w < WARPS_B; w++) {
            float4 v = se[w][tid];
            acc.x += v.x; acc.y += v.y; acc.z += v.z; acc.w += v.w;
        }
        g_epartT[tid * GRID + cta] = acc;      // position-major for phase 3
        if (tid == 0) {
            float z = 0.f;
#pragma unroll
            for (int w = 0; w < WARPS_B; w++) z += sZ[w];
            g_Zpart[cta] = z;
        }
    }
    gbar(1);

    // -------- Phase 3 (CTAs 0..127 + CTA 256) overlapped with W1 preload ----
    float4 a[8]; float bj = 0.f, dj = 0.f;     // phase-4 preloads (CTAs 128..255)
    if (cta >= 128 && cta < 256) {
        int j = (cta - 128) * WARPS_B + wid;   // 0..1023
        const float4* w1r = (const float4*)(W1 + (size_t)j * HD);
#pragma unroll
        for (int k = 0; k < 8; k++) a[k] = w1r[lane + 32 * k];  // 4MB overlaps ph3
        if (lane == 0) { bj = b1[j]; dj = __ldcg(g_d2 + j); }
    } else if (cta < 128) {                    // reduce 2 positions per CTA
        int g = tid >> 7, t0 = tid & 127;      // g in {0,1}
        int p = 2 * cta + g;
        const float4* src = g_epartT + (size_t)p * GRID;
        float4 acc = __ldcg(src + t0);
        {   float4 v = __ldcg(src + t0 + 128);
            acc.x += v.x; acc.y += v.y; acc.z += v.z; acc.w += v.w; }
        if (t0 < GRID - 256) {
            float4 v = __ldcg(src + t0 + 256);
            acc.x += v.x; acc.y += v.y; acc.z += v.z; acc.w += v.w;
        }
        float4* red = &se[g * 2][0];           // two disjoint 128-entry buffers
        red[t0] = acc;
        __syncthreads();
#pragma unroll
        for (int o = 64; o; o >>= 1) {
            if (t0 < o) {
                float4 v = red[t0 + o], t = red[t0];
                t.x += v.x; t.y += v.y; t.z += v.z; t.w += v.w;
                red[t0] = t;
            }
            __syncthreads();
        }
        if (t0 == 0) ((float4*)g_es)[p] = red[0];
    } else if (cta == 256) {                   // partition function
        if (wid == 0) {
            float z = 0.f;
            for (int b = lane; b < GRID; b += 32) z += __ldcg(g_Zpart + b);
#pragma unroll
            for (int o = 16; o; o >>= 1) z += __shfl_xor_sync(0xffffffffu, z, o);
            if (lane == 0) g_Zsum = z;
        }
    }
    gbar(2);

    // ---------------- Phase 4: out = tanh(W1@e_s/Z + b1 + d2) ----------------
    if (cta >= 128 && cta < 256) {
        int j = (cta - 128) * WARPS_B + wid;
        sv[tid] = __ldcg(((const float4*)g_es) + tid);
        if (tid == 0) sZtot = __ldcg(&g_Zsum);
        __syncthreads();

        float d1 = 0.f;
#pragma unroll
        for (int k = 0; k < 8; k++) {
            float4 v = sv[lane + 32 * k];
            d1 = fmaf(a[k].x, v.x, d1); d1 = fmaf(a[k].y, v.y, d1);
            d1 = fmaf(a[k].z, v.z, d1); d1 = fmaf(a[k].w, v.w, d1);
        }
#pragma unroll
        for (int o = 16; o; o >>= 1) d1 += __shfl_xor_sync(0xffffffffu, d1, o);
        if (lane == 0)
            out[j] = tanhf(d1 / sZtot + bj + dj);
    }
}

// ---------------------------------------------------------------------------
extern "C" void kernel_launch(void* const* d_in, const int* in_sizes, int n_in,
                              void* d_out, int out_size) {
    const float* H  = (const float*)d_in[0];
    const float* ht = (const float*)d_in[1];
    const float* W0 = (const float*)d_in[2];
    const float* b0 = (const float*)d_in[3];
    const float* W1 = (const float*)d_in[4];
    const float* b1 = (const float*)d_in[5];
    const float* W2 = (const float*)d_in[6];
    const float* b2 = (const float*)d_in[7];
    float* out = (float*)d_out;

    fused<<<GRID, 256>>>(H, ht, W0, b0, W1, b1, W2, b2, out);
}

// round 12
// speedup vs baseline: 1.2682x; 1.0139x over previous
#include <cuda_runtime.h>
#include <math.h>

#define HD      1024
#define NROWS   50000
#define GRID    288                  // 2 CTAs/SM on >=144 SMs: co-residency safe
#define WARPS_B 8
#define TOT_WARPS (GRID * WARPS_B)   // 2304
#define NP4     (HD / 4)             // 256 float4 per vector
#define PF_ITERS 3                   // startup prefetch depth (iterations)

// Scratch (__device__ globals)
__device__ float  g_q[HD];
__device__ float  g_d2[HD];                     // W2@h_t + b2
__device__ float4 g_epartT[NP4 * GRID];         // [position][cta]
__device__ float  g_Zpart[GRID];
__device__ float  g_es[HD];
__device__ float  g_Zsum;
__device__ unsigned g_ctr[4];                   // barrier counters (monotonic)

// Grid-wide barrier, graph-replay safe: counter never resets.
__device__ __forceinline__ void gbar(int k) {
    __syncthreads();
    if (threadIdx.x == 0) {
        __threadfence();
        unsigned old = atomicAdd(&g_ctr[k], 1u);
        unsigned target = old - (old % GRID) + GRID;
        while (*(volatile unsigned*)&g_ctr[k] < target) { }
    }
    __syncthreads();
    __threadfence();
}

__device__ __forceinline__ float4 ldcs4(const float4* p) {
    float4 v;
    asm volatile("ld.global.cs.v4.f32 {%0,%1,%2,%3}, [%4];"
                 : "=f"(v.x), "=f"(v.y), "=f"(v.z), "=f"(v.w) : "l"(p));
    return v;
}
__device__ __forceinline__ void pfL2(const void* p) {
    asm volatile("prefetch.global.L2 [%0];" :: "l"(p));
}

__global__ __launch_bounds__(256, 2) void fused(
    const float* __restrict__ H,  const float* __restrict__ ht,
    const float* __restrict__ W0, const float* __restrict__ b0,
    const float* __restrict__ W1, const float* __restrict__ b1,
    const float* __restrict__ W2, const float* __restrict__ b2,
    float* __restrict__ out)
{
    __shared__ float4 sv[NP4];                 // ht -> q -> e_s (phase-local)
    __shared__ float4 se[WARPS_B][NP4];        // warp partials / reduce buf
    __shared__ float  sZ[WARPS_B];
    __shared__ float  sZtot;

    const int tid  = threadIdx.x;
    const int wid  = tid >> 5, lane = tid & 31;
    const int cta  = blockIdx.x;
    const int gw   = cta * WARPS_B + wid;      // global warp id, 0..2303

    // ---------------- Phase 1: q = W0@ht + b0 ; d2 = W2@ht + b2 --------------
    sv[tid] = ((const float4*)ht)[tid];
    __syncthreads();
    {
        if (gw < 2048) {
            int j = gw & 1023;
            const float* W = (gw < 1024) ? W0 : W2;
            const float* b = (gw < 1024) ? b0 : b2;
            const float4* wr = (const float4*)(W + (size_t)j * HD);
            float4 w[8];
#pragma unroll
            for (int k = 0; k < 8; k++) w[k] = wr[lane + 32 * k];  // MLP=8

            // Startup prefetch: this warp's first PF_ITERS phase-2 iterations.
#pragma unroll
            for (int it = 0; it < PF_ITERS; it++) {
                long r0 = 2L * gw + it * (2L * TOT_WARPS);
                if (r0 + 1 < NROWS) {
                    pfL2(H + r0 * HD + lane * 32);
                    pfL2(H + (r0 + 1) * HD + lane * 32);
                }
            }

            float s = 0.f;
#pragma unroll
            for (int k = 0; k < 8; k++) {
                float4 h4 = sv[lane + 32 * k];
                s = fmaf(w[k].x, h4.x, s); s = fmaf(w[k].y, h4.y, s);
                s = fmaf(w[k].z, h4.z, s); s = fmaf(w[k].w, h4.w, s);
            }
#pragma unroll
            for (int o = 16; o; o >>= 1) s += __shfl_xor_sync(0xffffffffu, s, o);
            if (lane == 0) { if (gw < 1024) g_q[j] = s + b[j]; else g_d2[j] = s + b[j]; }
        } else {
#pragma unroll
            for (int it = 0; it < PF_ITERS; it++) {
                long r0 = 2L * gw + it * (2L * TOT_WARPS);
                if (r0 + 1 < NROWS) {
                    pfL2(H + r0 * HD + lane * 32);
                    pfL2(H + (r0 + 1) * HD + lane * 32);
                }
            }
        }
    }
    gbar(0);

    // ---------------- Phase 2: pass over H, TWO rows per warp-iteration ------
    // In-loop L2 prefetch keeps the DRAM->L2 pipe running 2 iterations ahead;
    // demand LDGs then mostly hit L2 (~250cyc) instead of DRAM (~600cyc).
    sv[tid] = __ldcg(((const float4*)g_q) + tid);
    __syncthreads();

    float4 e[8];
#pragma unroll
    for (int k = 0; k < 8; k++) e[k] = make_float4(0.f, 0.f, 0.f, 0.f);
    float Z = 0.f;

    const long pfoff = 2L * (PF_ITERS - 1) * TOT_WARPS * HD;   // rows at iter+PF-1
    for (int row = 2 * gw; row < NROWS; row += 2 * TOT_WARPS) {
        const float* hb = H + (size_t)row * HD;
        const float4* h0 = (const float4*)hb;
        const float4* h1 = (const float4*)(hb + HD);

        // prefetch the rows this warp will read PF_ITERS-1 iterations ahead
        {
            const float* pf = hb + pfoff + lane * 32;
            if (row + 2 * (PF_ITERS - 1) * TOT_WARPS + 1 < NROWS) {
                pfL2(pf);
                pfL2(pf + HD);
            }
        }

        float4 r0[8], r1[8];
#pragma unroll
        for (int k = 0; k < 8; k++) r0[k] = ldcs4(h0 + lane + 32 * k);  // 16 loads
#pragma unroll
        for (int k = 0; k < 8; k++) r1[k] = ldcs4(h1 + lane + 32 * k);  // front-batched

        float s0 = 0.f, s1 = 0.f;
#pragma unroll
        for (int k = 0; k < 8; k++) {
            float4 q4 = sv[lane + 32 * k];
            s0 = fmaf(r0[k].x, q4.x, s0); s0 = fmaf(r0[k].y, q4.y, s0);
            s0 = fmaf(r0[k].z, q4.z, s0); s0 = fmaf(r0[k].w, q4.w, s0);
            s1 = fmaf(r1[k].x, q4.x, s1); s1 = fmaf(r1[k].y, q4.y, s1);
            s1 = fmaf(r1[k].z, q4.z, s1); s1 = fmaf(r1[k].w, q4.w, s1);
        }
#pragma unroll
        for (int o = 16; o; o >>= 1) {
            s0 += __shfl_xor_sync(0xffffffffu, s0, o);
            s1 += __shfl_xor_sync(0xffffffffu, s1, o);
        }

        // double exp; softmax(t)=exp(t)/sum(exp(t)) exactly, t bounded.
        float u0 = expf(expf(s0));
        float u1 = expf(expf(s1));
        Z += u0 + u1;
#pragma unroll
        for (int k = 0; k < 8; k++) {
            e[k].x = fmaf(u0, r0[k].x, fmaf(u1, r1[k].x, e[k].x));
            e[k].y = fmaf(u0, r0[k].y, fmaf(u1, r1[k].y, e[k].y));
            e[k].z = fmaf(u0, r0[k].z, fmaf(u1, r1[k].z, e[k].z));
            e[k].w = fmaf(u0, r0[k].w, fmaf(u1, r1[k].w, e[k].w));
        }
    }

    // CTA-level deterministic reduce of the 8 warp partials
#pragma unroll
    for (int k = 0; k < 8; k++) se[wid][lane + 32 * k] = e[k];
    if (lane == 0) sZ[wid] = Z;
    __syncthreads();
    {
        float4 acc = se[0][tid];
#pragma unroll
        for (int w = 1; w < WARPS_B; w++) {
            float4 v = se[w][tid];
            acc.x += v.x; acc.y += v.y; acc.z += v.z; acc.w += v.w;
        }
        g_epartT[tid * GRID + cta] = acc;      // position-major for phase 3
        if (tid == 0) {
            float z = 0.f;
#pragma unroll
            for (int w = 0; w < WARPS_B; w++) z += sZ[w];
            g_Zpart[cta] = z;
        }
    }
    gbar(1);

    // -------- Phase 3 (CTAs 0..127 + CTA 256) overlapped with W1 preload ----
    float4 a[8]; float bj = 0.f, dj = 0.f;     // phase-4 preloads (CTAs 128..255)
    if (cta >= 128 && cta < 256) {
        int j = (cta - 128) * WARPS_B + wid;   // 0..1023
        const float4* w1r = (const float4*)(W1 + (size_t)j * HD);
#pragma unroll
        for (int k = 0; k < 8; k++) a[k] = w1r[lane + 32 * k];  // 4MB overlaps ph3
        if (lane == 0) { bj = b1[j]; dj = __ldcg(g_d2 + j); }
    } else if (cta < 128) {                    // reduce 2 positions per CTA
        int g = tid >> 7, t0 = tid & 127;      // g in {0,1}
        int p = 2 * cta + g;
        const float4* src = g_epartT + (size_t)p * GRID;
        float4 acc = __ldcg(src + t0);
        {   float4 v = __ldcg(src + t0 + 128);
            acc.x += v.x; acc.y += v.y; acc.z += v.z; acc.w += v.w; }
        if (t0 < GRID - 256) {
            float4 v = __ldcg(src + t0 + 256);
            acc.x += v.x; acc.y += v.y; acc.z += v.z; acc.w += v.w;
        }
        float4* red = &se[g * 2][0];           // two disjoint 128-entry buffers
        red[t0] = acc;
        __syncthreads();
#pragma unroll
        for (int o = 64; o; o >>= 1) {
            if (t0 < o) {
                float4 v = red[t0 + o], t = red[t0];
                t.x += v.x; t.y += v.y; t.z += v.z; t.w += v.w;
                red[t0] = t;
            }
            __syncthreads();
        }
        if (t0 == 0) ((float4*)g_es)[p] = red[0];
    } else if (cta == 256) {                   // partition function
        if (wid == 0) {
            float z = 0.f;
            for (int b = lane; b < GRID; b += 32) z += __ldcg(g_Zpart + b);
#pragma unroll
            for (int o = 16; o; o >>= 1) z += __shfl_xor_sync(0xffffffffu, z, o);
            if (lane == 0) g_Zsum = z;
        }
    }
    gbar(2);

    // ---------------- Phase 4: out = tanh(W1@e_s/Z + b1 + d2) ----------------
    if (cta >= 128 && cta < 256) {
        int j = (cta - 128) * WARPS_B + wid;
        sv[tid] = __ldcg(((const float4*)g_es) + tid);
        if (tid == 0) sZtot = __ldcg(&g_Zsum);
        __syncthreads();

        float d1 = 0.f;
#pragma unroll
        for (int k = 0; k < 8; k++) {
            float4 v = sv[lane + 32 * k];
            d1 = fmaf(a[k].x, v.x, d1); d1 = fmaf(a[k].y, v.y, d1);
            d1 = fmaf(a[k].z, v.z, d1); d1 = fmaf(a[k].w, v.w, d1);
        }
#pragma unroll
        for (int o = 16; o; o >>= 1) d1 += __shfl_xor_sync(0xffffffffu, d1, o);
        if (lane == 0)
            out[j] = tanhf(d1 / sZtot + bj + dj);
    }
}

// ---------------------------------------------------------------------------
extern "C" void kernel_launch(void* const* d_in, const int* in_sizes, int n_in,
                              void* d_out, int out_size) {
    const float* H  = (const float*)d_in[0];
    const float* ht = (const float*)d_in[1];
    const float* W0 = (const float*)d_in[2];
    const float* b0 = (const float*)d_in[3];
    const float* W1 = (const float*)d_in[4];
    const float* b1 = (const float*)d_in[5];
    const float* W2 = (const float*)d_in[6];
    const float* b2 = (const float*)d_in[7];
    float* out = (float*)d_out;

    fused<<<GRID, 256>>>(H, ht, W0, b0, W1, b1, W2, b2, out);
}